// round 9
// baseline (speedup 1.0000x reference)
#include <cuda_runtime.h>
#include <math.h>

#define TOKENS 288
#define DM 512
#define NE 16
#define KTOP 4
#define NPAIR (3*TOKENS*KTOP)   // 3456
#define LCAP 1024
#define HID 2048
#define DSPLIT 2

// ---------------- scratch (device globals; allocation-free) ----------------
__device__ float g_views[3*TOKENS*DM];
__device__ float g_pw[NPAIR];
__device__ int   g_counts[NE];
__device__ int   g_lists[NE*LCAP];
__device__ float g_h[(size_t)NPAIR*HID];                 // 28 MB
__device__ float g_ypart[(size_t)DSPLIT*NPAIR*DM];       // 14 MB
__device__ float g_part[(size_t)16*TOKENS*HID];          // split-K partials
__device__ float g_x[TOKENS*DM];
__device__ float g_attno[TOKENS*DM];
__device__ float g_hid[TOKENS*HID];

__global__ void zero_kernel() { if (threadIdx.x < NE) g_counts[threadIdx.x] = 0; }

// ---------------- f32x2 helpers ----------------
__device__ __forceinline__ unsigned long long dup2(float a) {
    unsigned long long r; asm("mov.b64 %0, {%1,%1};" : "=l"(r) : "f"(a)); return r;
}
__device__ __forceinline__ unsigned long long fma2(unsigned long long a, unsigned long long b,
                                                   unsigned long long c) {
    unsigned long long d;
    asm("fma.rn.f32x2 %0, %1, %2, %3;" : "=l"(d) : "l"(a), "l"(b), "l"(c));
    return d;
}
__device__ __forceinline__ void unpack2(unsigned long long v, float& lo, float& hi) {
    asm("mov.b64 {%0,%1}, %2;" : "=f"(lo), "=f"(hi) : "l"(v));
}

// ---------------- fused embedding + routing ----------------
__global__ void embed_route_kernel(const int* __restrict__ Z,
    const float* __restrict__ e0, const float* __restrict__ p0, const float* __restrict__ b0,
    const float* __restrict__ e1, const float* __restrict__ p1, const float* __restrict__ b1,
    const float* __restrict__ e2, const float* __restrict__ p2, const float* __restrict__ b2,
    const float* __restrict__ keys, const float* __restrict__ rw, const float* __restrict__ rb)
{
    int t = blockIdx.x, view = blockIdx.y;
    const float *emb, *pw, *pb; int F;
    if (view == 0)      { emb = e0; pw = p0; pb = b0; F = 200; }
    else if (view == 1) { emb = e1; pw = p1; pb = b1; F = 132; }
    else                { emb = e2; pw = p2; pb = b2; F = 112; }
    __shared__ float er[200];
    __shared__ float vs[DM];
    __shared__ float logits[NE];
    int z = Z[t];
    for (int f = threadIdx.x; f < F; f += blockDim.x) er[f] = emb[z*F + f];
    __syncthreads();
    for (int d = threadIdx.x; d < DM; d += blockDim.x) {
        float acc = pb[d];
        for (int f = 0; f < F; f++) acc = fmaf(er[f], pw[f*DM + d], acc);
        vs[d] = acc;
        g_views[(view*TOKENS + t)*DM + d] = acc;
    }
    __syncthreads();
    int warp = threadIdx.x >> 5, lane = threadIdx.x & 31;
    for (int e = warp; e < NE; e += 8) {
        float a = 0.f, b = 0.f;
        for (int d = lane; d < DM; d += 32) {
            float kk = keys[e*DM + d];
            a = fmaf(vs[d], 2.f*kk + rw[(view*DM + d)*NE + e], a);
            b = fmaf(kk, kk, b);
        }
        #pragma unroll
        for (int o = 16; o; o >>= 1) {
            a += __shfl_down_sync(0xffffffffu, a, o);
            b += __shfl_down_sync(0xffffffffu, b, o);
        }
        if (lane == 0) logits[e] = a - b + rb[view*NE + e];
    }
    __syncthreads();
    if (threadIdx.x == 0) {
        float vals[KTOP]; int idx[KTOP]; bool used[NE];
        for (int e = 0; e < NE; e++) used[e] = false;
        for (int k = 0; k < KTOP; k++) {
            float best = -1e30f; int bi = 0;
            for (int e = 0; e < NE; e++)
                if (!used[e] && logits[e] > best) { best = logits[e]; bi = e; }
            used[bi] = true; vals[k] = best; idx[k] = bi;
        }
        float m = vals[0], s = 0.f, w[KTOP];
        for (int k = 0; k < KTOP; k++) { w[k] = expf(vals[k] - m); s += w[k]; }
        float inv = 1.f / s;
        for (int k = 0; k < KTOP; k++) {
            int slot = (view*TOKENS + t)*KTOP + k;
            g_pw[slot] = w[k] * inv;
            int pos = atomicAdd(&g_counts[idx[k]], 1);
            if (pos < LCAP) g_lists[idx[k]*LCAP + pos] = slot;
        }
    }
}

// ---------------- GEMM: 64x128 tile, KTILE=32, 256 thr, 4x8 micro via f32x2 ----
// 3 CTAs/SM; one __syncthreads pair per 32-K tile (half the barriers of R8).
// MODE 0: dense (blockIdx.z = split s; C=[s][M][N] raw partials)
// MODE 1: moe up (z = expert; gather g_views rows via g_lists slot>>2; out g_h[slot]; bias+gelu)
// MODE 2: moe down (z = e*SPLITS+s; gather g_h rows slot; C=[s][NPAIR][N]; bias at s==0)
#define KTILE 32
template<int MODE, int ACT, int SPLITS>
__global__ void __launch_bounds__(256, 3) gemm_kernel(
    const float* __restrict__ A, const float* __restrict__ W,
    const float* __restrict__ bias, float* __restrict__ C,
    int M, int N, int K)
{
    int e = 0, s = 0;
    if (MODE == 2)      { e = blockIdx.z / SPLITS; s = blockIdx.z % SPLITS; }
    else if (MODE == 1) { e = blockIdx.z; }
    else                { s = blockIdx.z; }

    int nBase = blockIdx.x * 128, mBase = blockIdx.y * 64;
    int Mcur = M;
    __shared__ int rs[64];
    __shared__ __align__(16) float As[KTILE][68];
    __shared__ __align__(16) float Bs[KTILE][128];

    if (MODE != 0) {
        Mcur = g_counts[e];
        if (mBase >= Mcur) return;
        W    += (size_t)e * K * N;
        bias += (size_t)e * N;
        if (threadIdx.x < 64) {
            int gm = mBase + threadIdx.x;
            rs[threadIdx.x] = (gm < Mcur) ? g_lists[e*LCAP + gm] : g_lists[e*LCAP];
        }
        __syncthreads();
    }

    const int tid = threadIdx.x;
    const int tr = tid >> 4, tc = tid & 15;        // compute: m-group 0..15, n-col 0..15
    const int lr = tid >> 2, lk4 = (tid & 3) * 4;  // A-load: row 0..63, k-quad (per 16-k pass)
    const int wr = tid >> 4, wc = (tid & 15) * 8;  // B-load: k-row 0..15 (per pass)

    const int kChunk = K / SPLITS;
    const int kStart = s * kChunk, kEnd = kStart + kChunk;

    const float* Arow;
    bool rv;
    {
        int gm = mBase + lr;
        rv = gm < Mcur;
        int ar = 0;
        if (rv) {
            if (MODE == 0)      ar = gm;
            else if (MODE == 1) ar = rs[lr] >> 2;
            else                ar = rs[lr];
        }
        Arow = A + (size_t)ar * K;
    }
    const float* Wp = W + nBase + wc;

    unsigned long long acc[4][4];
    #pragma unroll
    for (int i = 0; i < 4; i++)
        #pragma unroll
        for (int j = 0; j < 4; j++) acc[i][j] = 0ull;

    for (int k0 = kStart; k0 < kEnd; k0 += KTILE) {
        // stage A+B for 32 k-rows (two 16-k passes)
        #pragma unroll
        for (int p = 0; p < 2; p++) {
            int kb = p * 16;
            float4 av = rv ? *(const float4*)(Arow + k0 + kb + lk4) : make_float4(0,0,0,0);
            As[kb+lk4+0][lr] = av.x; As[kb+lk4+1][lr] = av.y;
            As[kb+lk4+2][lr] = av.z; As[kb+lk4+3][lr] = av.w;
            const float* wp = Wp + (size_t)(k0 + kb + wr) * N;
            *(float4*)(&Bs[kb+wr][wc])     = *(const float4*)(wp);
            *(float4*)(&Bs[kb+wr][wc + 4]) = *(const float4*)(wp + 4);
        }
        __syncthreads();
        #pragma unroll
        for (int k = 0; k < KTILE; k++) {
            float4 a4 = *(const float4*)(&As[k][tr*4]);
            ulonglong2 b0 = *(const ulonglong2*)(&Bs[k][tc*4]);
            ulonglong2 b1 = *(const ulonglong2*)(&Bs[k][64 + tc*4]);
            unsigned long long da[4];
            da[0] = dup2(a4.x); da[1] = dup2(a4.y); da[2] = dup2(a4.z); da[3] = dup2(a4.w);
            #pragma unroll
            for (int i = 0; i < 4; i++) {
                acc[i][0] = fma2(da[i], b0.x, acc[i][0]);
                acc[i][1] = fma2(da[i], b0.y, acc[i][1]);
                acc[i][2] = fma2(da[i], b1.x, acc[i][2]);
                acc[i][3] = fma2(da[i], b1.y, acc[i][3]);
            }
        }
        __syncthreads();
    }

    #pragma unroll
    for (int i = 0; i < 4; i++) {
        int mloc = tr*4 + i;
        int m = mBase + mloc;
        if (m >= Mcur) continue;
        size_t crow;
        if (MODE == 0)      crow = ((size_t)s * M + m) * N;
        else if (MODE == 1) crow = (size_t)rs[mloc] * N;
        else                crow = ((size_t)s * NPAIR + rs[mloc]) * N;
        #pragma unroll
        for (int j = 0; j < 4; j++) {
            int n = nBase + ((j < 2) ? (tc*4 + j*2) : (64 + tc*4 + (j - 2)*2));
            float lo, hi; unpack2(acc[i][j], lo, hi);
            if (MODE == 1 || (MODE == 2 && s == 0)) { lo += bias[n]; hi += bias[n+1]; }
            if (ACT == 1) {
                lo = 0.5f*lo*(1.f + erff(lo*0.7071067811865476f));
                hi = 0.5f*hi*(1.f + erff(hi*0.7071067811865476f));
            }
            *(float2*)(C + crow + n) = make_float2(lo, hi);
        }
    }
}

// ---------------- split-K reduce + bias (+relu) ----------------
template<int ACT>
__global__ void reduce_bias_kernel(const float* __restrict__ part, const float* __restrict__ bias,
                                   float* __restrict__ out, int M, int N, int S)
{
    int idx = blockIdx.x * 256 + threadIdx.x;
    if (idx >= M * N) return;
    int n = idx % N;
    float acc = bias[n];
    for (int s = 0; s < S; s++) acc += part[(size_t)s * M * N + idx];
    if (ACT == 2) acc = fmaxf(acc, 0.f);
    out[idx] = acc;
}

// ---------------- MoE combine + fractional positional encoding ----------------
__global__ void combine_kernel(const float* __restrict__ frac)
{
    int t = blockIdx.x, d = threadIdx.x;
    float acc = 0.f;
    #pragma unroll
    for (int view = 0; view < 3; view++)
        #pragma unroll
        for (int k = 0; k < KTOP; k++) {
            int slot = (view*TOKENS + t)*KTOP + k;
            float y = 0.f;
            #pragma unroll
            for (int s = 0; s < DSPLIT; s++)
                y += g_ypart[((size_t)s * NPAIR + slot)*DM + d];
            acc = fmaf(g_pw[slot], y, acc);
        }
    float fr = frac[t];
    int j; float r;
    if (d < 256) { j = d; r = fr; }
    else {
        j = d - 256;
        float l = log2f(fr);
        r = fminf(0.0025f * l * l, 1.0f);
    }
    r = fmaxf(r, 0.0002f);
    int idx = (int)rintf(r * 5000.0f) - 1;
    idx = max(0, min(4999, idx));
    double dv = pow(50.0, (double)(2*j) / 256.0);
    float pe = (float)((j & 1) ? cos((double)idx / dv) : sin((double)idx / dv));
    g_x[t*DM + d] = acc + pe;
}

// ---------------- attention (folds qkv split-K reduce + bias) ----------------
__global__ void attn_kernel(const float* __restrict__ part, const float* __restrict__ qb)
{
    int b = blockIdx.x, h = blockIdx.y;
    __shared__ float q[9][64], k[9][64], v[9][64], s[9][9];
    for (int i = threadIdx.x; i < 9*64; i += blockDim.x) {
        int l = i >> 6, d = i & 63;
        size_t row = (size_t)(b*9 + l)*1536 + h*64 + d;
        float qq = qb[h*64 + d], kk = qb[512 + h*64 + d], vv = qb[1024 + h*64 + d];
        #pragma unroll
        for (int sp = 0; sp < 4; sp++) {
            size_t o = (size_t)sp*TOKENS*1536 + row;
            qq += part[o]; kk += part[o + 512]; vv += part[o + 1024];
        }
        q[l][d] = qq; k[l][d] = kk; v[l][d] = vv;
    }
    __syncthreads();
    for (int i = threadIdx.x; i < 81; i += blockDim.x) {
        int qi = i / 9, kj = i % 9; float a = 0.f;
        #pragma unroll
        for (int d = 0; d < 64; d++) a = fmaf(q[qi][d], k[kj][d], a);
        s[qi][kj] = a * 0.125f;
    }
    __syncthreads();
    if (threadIdx.x < 9) {
        int i = threadIdx.x;
        float m = s[i][0];
        for (int jj = 1; jj < 9; jj++) m = fmaxf(m, s[i][jj]);
        float sum = 0.f;
        for (int jj = 0; jj < 9; jj++) { float ee = expf(s[i][jj] - m); s[i][jj] = ee; sum += ee; }
        float inv = 1.f / sum;
        for (int jj = 0; jj < 9; jj++) s[i][jj] *= inv;
    }
    __syncthreads();
    for (int i = threadIdx.x; i < 9*64; i += blockDim.x) {
        int l = i >> 6, d = i & 63; float a = 0.f;
        #pragma unroll
        for (int jj = 0; jj < 9; jj++) a = fmaf(s[l][jj], v[jj][d], a);
        g_attno[(size_t)(b*9 + l)*DM + h*64 + d] = a;
    }
}

// ---------------- split-K reduce + residual + LayerNorm ----------------
__device__ __forceinline__ float blockSum(float v, float* red)
{
    int lane = threadIdx.x & 31, w = threadIdx.x >> 5;
    #pragma unroll
    for (int o = 16; o; o >>= 1) v += __shfl_down_sync(0xffffffffu, v, o);
    if (lane == 0) red[w] = v;
    __syncthreads();
    if (threadIdx.x == 0) { float ss = 0.f; for (int i = 0; i < 8; i++) ss += red[i]; red[0] = ss; }
    __syncthreads();
    float r = red[0];
    __syncthreads();
    return r;
}

__global__ void reduce_addln_kernel(const float* __restrict__ part, int S,
                                    const float* __restrict__ bias,
                                    const float* __restrict__ gam, const float* __restrict__ bet,
                                    float* __restrict__ fout, const float* __restrict__ frac)
{
    int t = blockIdx.x, tid = threadIdx.x;
    __shared__ float red[8];
    float y0 = bias[tid], y1 = bias[tid + 256];
    for (int s = 0; s < S; s++) {
        y0 += part[((size_t)s*TOKENS + t)*DM + tid];
        y1 += part[((size_t)s*TOKENS + t)*DM + tid + 256];
    }
    float s0 = g_x[t*DM + tid] + y0;
    float s1 = g_x[t*DM + tid + 256] + y1;
    float mean = blockSum(s0 + s1, red) * (1.f/512.f);
    float d0 = s0 - mean, d1 = s1 - mean;
    float var = blockSum(d0*d0 + d1*d1, red) * (1.f/512.f);
    float inv = rsqrtf(var + 1e-5f);
    float r0 = d0*inv*gam[tid]       + bet[tid];
    float r1 = d1*inv*gam[tid + 256] + bet[tid + 256];
    if (fout) {
        float fr = frac[t];
        fout[t*DM + tid]       = r0 * fr;
        fout[t*DM + tid + 256] = r1 * fr;
    } else {
        g_x[t*DM + tid]       = r0;
        g_x[t*DM + tid + 256] = r1;
    }
}

// ---------------------------------- host ----------------------------------
extern "C" void kernel_launch(void* const* d_in, const int* in_sizes, int n_in,
                              void* d_out, int out_size)
{
    const int*   Z    = (const int*)d_in[0];
    const float* frac = (const float*)d_in[1];
    const float *emb0, *p0w, *p0b, *emb1, *p1w, *p1b, *emb2, *p2w, *p2b;
    if (in_sizes[3] == 200*512) {
        emb0 = (const float*)d_in[2]; p0w = (const float*)d_in[3]; p0b = (const float*)d_in[4];
        emb1 = (const float*)d_in[5]; p1w = (const float*)d_in[6]; p1b = (const float*)d_in[7];
        emb2 = (const float*)d_in[8]; p2w = (const float*)d_in[9]; p2b = (const float*)d_in[10];
    } else {
        emb0 = (const float*)d_in[2]; emb1 = (const float*)d_in[3]; emb2 = (const float*)d_in[4];
        p0w = (const float*)d_in[5]; p0b = (const float*)d_in[6];
        p1w = (const float*)d_in[7]; p1b = (const float*)d_in[8];
        p2w = (const float*)d_in[9]; p2b = (const float*)d_in[10];
    }
    const float* keys = (const float*)d_in[11];
    const float* rw   = (const float*)d_in[12];
    const float* rb   = (const float*)d_in[13];
    const float* ew1  = (const float*)d_in[14];
    const float* eb1  = (const float*)d_in[15];
    const float* ew2  = (const float*)d_in[16];
    const float* eb2  = (const float*)d_in[17];
    const float* qkvw = (const float*)d_in[18];
    const float* qkvb = (const float*)d_in[19];
    const float* aow  = (const float*)d_in[20];
    const float* aob  = (const float*)d_in[21];
    const float* l1g  = (const float*)d_in[22];
    const float* l1b  = (const float*)d_in[23];
    const float* l2g  = (const float*)d_in[24];
    const float* l2b  = (const float*)d_in[25];
    const float* f1w  = (const float*)d_in[26];
    const float* f1b  = (const float*)d_in[27];
    const float* f2w  = (const float*)d_in[28];
    const float* f2b  = (const float*)d_in[29];

    float *p_views, *p_h, *p_ypart, *p_part, *p_x, *p_attno, *p_hid;
    cudaGetSymbolAddress((void**)&p_views, g_views);
    cudaGetSymbolAddress((void**)&p_h,     g_h);
    cudaGetSymbolAddress((void**)&p_ypart, g_ypart);
    cudaGetSymbolAddress((void**)&p_part,  g_part);
    cudaGetSymbolAddress((void**)&p_x,     g_x);
    cudaGetSymbolAddress((void**)&p_attno, g_attno);
    cudaGetSymbolAddress((void**)&p_hid,   g_hid);

    zero_kernel<<<1, 32>>>();
    embed_route_kernel<<<dim3(TOKENS, 3), 256>>>(Z, emb0, p0w, p0b, emb1, p1w, p1b,
                                                 emb2, p2w, p2b, keys, rw, rb);

    // MoE up: gather + bias + gelu, full K=512
    gemm_kernel<1,1,1><<<dim3(HID/128, 14, NE), 256>>>(p_views, ew1, eb1, p_h, 0, HID, DM);
    // MoE down: split-K=2 over K=2048 (partials 14MB instead of 57MB)
    gemm_kernel<2,0,DSPLIT><<<dim3(DM/128, 14, NE*DSPLIT), 256>>>(p_h, ew2, eb2, p_ypart,
                                                                  0, DM, HID);
    combine_kernel<<<TOKENS, DM>>>(frac);

    for (int i = 0; i < 3; i++) {
        // qkv: split-K=4; reduce folded into attn
        gemm_kernel<0,0,4><<<dim3(12, 5, 4), 256>>>(p_x, qkvw + (size_t)i*DM*3*DM, nullptr,
                                                    p_part, TOKENS, 3*DM, DM);
        attn_kernel<<<dim3(32, 8), 128>>>(p_part, qkvb + (size_t)i*3*DM);
        // attn_out: split-K=8
        gemm_kernel<0,0,8><<<dim3(4, 5, 8), 256>>>(p_attno, aow + (size_t)i*DM*DM, nullptr,
                                                   p_part, TOKENS, DM, DM);
        reduce_addln_kernel<<<TOKENS, 256>>>(p_part, 8, aob + (size_t)i*DM,
                                             l1g + i*DM, l1b + i*DM, nullptr, nullptr);
        // ffn1: split-K=4, reduce+bias+relu -> g_hid
        gemm_kernel<0,0,4><<<dim3(16, 5, 4), 256>>>(p_x, f1w + (size_t)i*DM*HID, nullptr,
                                                    p_part, TOKENS, HID, DM);
        reduce_bias_kernel<2><<<(TOKENS*HID + 255)/256, 256>>>(p_part, f1b + (size_t)i*HID,
                                                               p_hid, TOKENS, HID, 4);
        // ffn2: split-K=16
        gemm_kernel<0,0,16><<<dim3(4, 5, 16), 256>>>(p_hid, f2w + (size_t)i*HID*DM, nullptr,
                                                     p_part, TOKENS, DM, HID);
        bool last = (i == 2);
        reduce_addln_kernel<<<TOKENS, 256>>>(p_part, 16, f2b + (size_t)i*DM,
                                             l2g + i*DM, l2b + i*DM,
                                             last ? (float*)d_out : nullptr,
                                             last ? frac : nullptr);
    }
}

// round 10
// speedup vs baseline: 1.1105x; 1.1105x over previous
#include <cuda_runtime.h>
#include <math.h>

#define TOKENS 288
#define DM 512
#define NE 16
#define KTOP 4
#define NPAIR (3*TOKENS*KTOP)   // 3456
#define LCAP 1024
#define HID 2048
#define DSPLIT 4

// ---------------- scratch (device globals; allocation-free) ----------------
__device__ float g_views[3*TOKENS*DM];
__device__ float g_pw[NPAIR];
__device__ int   g_counts[NE];
__device__ int   g_lists[NE*LCAP];
__device__ float g_h[(size_t)NPAIR*HID];                 // 28 MB
__device__ float g_ypart[(size_t)DSPLIT*NPAIR*DM];       // 28 MB
__device__ float g_part[(size_t)16*TOKENS*HID];          // dense split-K partials
__device__ float g_x[TOKENS*DM];
__device__ float g_attno[TOKENS*DM];
__device__ float g_hid[TOKENS*HID];

__global__ void zero_kernel() { if (threadIdx.x < NE) g_counts[threadIdx.x] = 0; }

// ---------------- f32x2 helpers ----------------
__device__ __forceinline__ unsigned long long dup2(float a) {
    unsigned long long r; asm("mov.b64 %0, {%1,%1};" : "=l"(r) : "f"(a)); return r;
}
__device__ __forceinline__ unsigned long long fma2(unsigned long long a, unsigned long long b,
                                                   unsigned long long c) {
    unsigned long long d;
    asm("fma.rn.f32x2 %0, %1, %2, %3;" : "=l"(d) : "l"(a), "l"(b), "l"(c));
    return d;
}
__device__ __forceinline__ void unpack2(unsigned long long v, float& lo, float& hi) {
    asm("mov.b64 {%0,%1}, %2;" : "=f"(lo), "=f"(hi) : "l"(v));
}

// ---------------- fused embedding + routing ----------------
__global__ void embed_route_kernel(const int* __restrict__ Z,
    const float* __restrict__ e0, const float* __restrict__ p0, const float* __restrict__ b0,
    const float* __restrict__ e1, const float* __restrict__ p1, const float* __restrict__ b1,
    const float* __restrict__ e2, const float* __restrict__ p2, const float* __restrict__ b2,
    const float* __restrict__ keys, const float* __restrict__ rw, const float* __restrict__ rb)
{
    int t = blockIdx.x, view = blockIdx.y;
    const float *emb, *pw, *pb; int F;
    if (view == 0)      { emb = e0; pw = p0; pb = b0; F = 200; }
    else if (view == 1) { emb = e1; pw = p1; pb = b1; F = 132; }
    else                { emb = e2; pw = p2; pb = b2; F = 112; }
    __shared__ float er[200];
    __shared__ float vs[DM];
    __shared__ float logits[NE];
    int z = Z[t];
    for (int f = threadIdx.x; f < F; f += blockDim.x) er[f] = emb[z*F + f];
    __syncthreads();
    for (int d = threadIdx.x; d < DM; d += blockDim.x) {
        float acc = pb[d];
        for (int f = 0; f < F; f++) acc = fmaf(er[f], pw[f*DM + d], acc);
        vs[d] = acc;
        g_views[(view*TOKENS + t)*DM + d] = acc;
    }
    __syncthreads();
    int warp = threadIdx.x >> 5, lane = threadIdx.x & 31;
    for (int e = warp; e < NE; e += 8) {
        float a = 0.f, b = 0.f;
        for (int d = lane; d < DM; d += 32) {
            float kk = keys[e*DM + d];
            a = fmaf(vs[d], 2.f*kk + rw[(view*DM + d)*NE + e], a);
            b = fmaf(kk, kk, b);
        }
        #pragma unroll
        for (int o = 16; o; o >>= 1) {
            a += __shfl_down_sync(0xffffffffu, a, o);
            b += __shfl_down_sync(0xffffffffu, b, o);
        }
        if (lane == 0) logits[e] = a - b + rb[view*NE + e];
    }
    __syncthreads();
    if (threadIdx.x == 0) {
        float vals[KTOP]; int idx[KTOP]; bool used[NE];
        for (int e = 0; e < NE; e++) used[e] = false;
        for (int k = 0; k < KTOP; k++) {
            float best = -1e30f; int bi = 0;
            for (int e = 0; e < NE; e++)
                if (!used[e] && logits[e] > best) { best = logits[e]; bi = e; }
            used[bi] = true; vals[k] = best; idx[k] = bi;
        }
        float m = vals[0], s = 0.f, w[KTOP];
        for (int k = 0; k < KTOP; k++) { w[k] = expf(vals[k] - m); s += w[k]; }
        float inv = 1.f / s;
        for (int k = 0; k < KTOP; k++) {
            int slot = (view*TOKENS + t)*KTOP + k;
            g_pw[slot] = w[k] * inv;
            int pos = atomicAdd(&g_counts[idx[k]], 1);
            if (pos < LCAP) g_lists[idx[k]*LCAP + pos] = slot;
        }
    }
}

// ---------------- staggered 16-k compute: warps use rotated k-order ----------
template<int OFF>
__device__ __forceinline__ void compute16(const float (*__restrict__ As)[136],
                                          const float (*__restrict__ Bs)[128],
                                          int tr, int tc, unsigned long long acc[8][4])
{
    #pragma unroll
    for (int kk = 0; kk < 16; kk++) {
        const int k = (kk + OFF) & 15;
        float4 aA = *(const float4*)(&As[k][tr*4]);
        float4 aB = *(const float4*)(&As[k][64 + tr*4]);
        ulonglong2 b0 = *(const ulonglong2*)(&Bs[k][tc*4]);
        ulonglong2 b1 = *(const ulonglong2*)(&Bs[k][64 + tc*4]);
        unsigned long long da[8];
        da[0]=dup2(aA.x); da[1]=dup2(aA.y); da[2]=dup2(aA.z); da[3]=dup2(aA.w);
        da[4]=dup2(aB.x); da[5]=dup2(aB.y); da[6]=dup2(aB.z); da[7]=dup2(aB.w);
        #pragma unroll
        for (int i = 0; i < 8; i++) {
            acc[i][0] = fma2(da[i], b0.x, acc[i][0]);
            acc[i][1] = fma2(da[i], b0.y, acc[i][1]);
            acc[i][2] = fma2(da[i], b1.x, acc[i][2]);
            acc[i][3] = fma2(da[i], b1.y, acc[i][3]);
        }
    }
}

// ---------------- GEMM: 128x128x16, 256 thr, 8x8 micro, dbuf + warp stagger ---
// MODE 0: dense (blockIdx.z = split s; C=[s][M][N] raw partials)
// MODE 1: moe up (z = expert; gather g_views rows via g_lists slot>>2; out g_h[slot]; bias+gelu)
// MODE 2: moe down (z = e*SPLITS+s; gather g_h rows slot; C=[s][NPAIR][N]; bias at s==0)
template<int MODE, int ACT, int SPLITS>
__global__ void __launch_bounds__(256, 2) gemm_kernel(
    const float* __restrict__ A, const float* __restrict__ W,
    const float* __restrict__ bias, float* __restrict__ C,
    int M, int N, int K)
{
    int e = 0, s = 0;
    if (MODE == 2)      { e = blockIdx.z / SPLITS; s = blockIdx.z % SPLITS; }
    else if (MODE == 1) { e = blockIdx.z; }
    else                { s = blockIdx.z; }

    int nBase = blockIdx.x * 128, mBase = blockIdx.y * 128;
    int Mcur = M;
    __shared__ int rs[128];
    __shared__ __align__(16) float As[2][16][136];
    __shared__ __align__(16) float Bs[2][16][128];

    if (MODE != 0) {
        Mcur = g_counts[e];
        if (mBase >= Mcur) return;
        W    += (size_t)e * K * N;
        bias += (size_t)e * N;
        if (threadIdx.x < 128) {
            int gm = mBase + threadIdx.x;
            rs[threadIdx.x] = (gm < Mcur) ? g_lists[e*LCAP + gm] : g_lists[e*LCAP];
        }
        __syncthreads();
    }

    const int tid = threadIdx.x;
    const int wid = tid >> 5;
    const int tr = tid >> 4, tc = tid & 15;
    const int lr = tid >> 1, lkq = (tid & 1) * 8;
    const int wr = tid >> 4, wc = (tid & 15) * 8;

    const int kChunk = K / SPLITS;
    const int kStart = s * kChunk, kEnd = kStart + kChunk;

    const float* Arow;
    bool rv;
    {
        int gm = mBase + lr;
        rv = gm < Mcur;
        int ar = 0;
        if (rv) {
            if (MODE == 0)      ar = gm;
            else if (MODE == 1) ar = rs[lr] >> 2;
            else                ar = rs[lr];
        }
        Arow = A + (size_t)ar * K;
    }
    const float* Wp = W + nBase + wc;

    unsigned long long acc[8][4];
    #pragma unroll
    for (int i = 0; i < 8; i++)
        #pragma unroll
        for (int j = 0; j < 4; j++) acc[i][j] = 0ull;

    // prologue: stage tile 0 into buffer 0
    float4 a0, a1, b0, b1;
    {
        a0 = rv ? *(const float4*)(Arow + kStart + lkq)     : make_float4(0,0,0,0);
        a1 = rv ? *(const float4*)(Arow + kStart + lkq + 4) : make_float4(0,0,0,0);
        const float* wp = Wp + (size_t)(kStart + wr) * N;
        b0 = *(const float4*)(wp);
        b1 = *(const float4*)(wp + 4);
    }
    As[0][lkq+0][lr]=a0.x; As[0][lkq+1][lr]=a0.y; As[0][lkq+2][lr]=a0.z; As[0][lkq+3][lr]=a0.w;
    As[0][lkq+4][lr]=a1.x; As[0][lkq+5][lr]=a1.y; As[0][lkq+6][lr]=a1.z; As[0][lkq+7][lr]=a1.w;
    *(float4*)(&Bs[0][wr][wc])     = b0;
    *(float4*)(&Bs[0][wr][wc + 4]) = b1;
    __syncthreads();

    int p = 0;
    for (int k0 = kStart; k0 < kEnd; k0 += 16) {
        const bool more = (k0 + 16) < kEnd;
        if (more) {
            a0 = rv ? *(const float4*)(Arow + k0 + 16 + lkq)     : make_float4(0,0,0,0);
            a1 = rv ? *(const float4*)(Arow + k0 + 16 + lkq + 4) : make_float4(0,0,0,0);
            const float* wp = Wp + (size_t)(k0 + 16 + wr) * N;
            b0 = *(const float4*)(wp);
            b1 = *(const float4*)(wp + 4);
        }
        // staggered compute: warps 0-3 start at k=0, warps 4-7 start at k=8
        if (wid < 4) compute16<0>(As[p], Bs[p], tr, tc, acc);
        else         compute16<8>(As[p], Bs[p], tr, tc, acc);
        if (more) {
            int q = p ^ 1;
            As[q][lkq+0][lr]=a0.x; As[q][lkq+1][lr]=a0.y; As[q][lkq+2][lr]=a0.z; As[q][lkq+3][lr]=a0.w;
            As[q][lkq+4][lr]=a1.x; As[q][lkq+5][lr]=a1.y; As[q][lkq+6][lr]=a1.z; As[q][lkq+7][lr]=a1.w;
            *(float4*)(&Bs[q][wr][wc])     = b0;
            *(float4*)(&Bs[q][wr][wc + 4]) = b1;
            __syncthreads();
            p = q;
        }
    }

    #pragma unroll
    for (int i = 0; i < 8; i++) {
        int mloc = (i < 4) ? (tr*4 + i) : (64 + tr*4 + (i - 4));
        int m = mBase + mloc;
        if (m >= Mcur) continue;
        size_t crow;
        if (MODE == 0)      crow = ((size_t)s * M + m) * N;
        else if (MODE == 1) crow = (size_t)rs[mloc] * N;
        else                crow = ((size_t)s * NPAIR + rs[mloc]) * N;
        #pragma unroll
        for (int j = 0; j < 4; j++) {
            int n = nBase + ((j < 2) ? (tc*4 + j*2) : (64 + tc*4 + (j - 2)*2));
            float lo, hi; unpack2(acc[i][j], lo, hi);
            if (MODE == 1 || (MODE == 2 && s == 0)) { lo += bias[n]; hi += bias[n+1]; }
            if (ACT == 1) {
                lo = 0.5f*lo*(1.f + erff(lo*0.7071067811865476f));
                hi = 0.5f*hi*(1.f + erff(hi*0.7071067811865476f));
            }
            *(float2*)(C + crow + n) = make_float2(lo, hi);
        }
    }
}

// ---------------- split-K reduce + bias (+relu) ----------------
template<int ACT>
__global__ void reduce_bias_kernel(const float* __restrict__ part, const float* __restrict__ bias,
                                   float* __restrict__ out, int M, int N, int S)
{
    int idx = blockIdx.x * 256 + threadIdx.x;
    if (idx >= M * N) return;
    int n = idx % N;
    float acc = bias[n];
    for (int s = 0; s < S; s++) acc += part[(size_t)s * M * N + idx];
    if (ACT == 2) acc = fmaxf(acc, 0.f);
    out[idx] = acc;
}

// ---------------- MoE combine + fractional positional encoding ----------------
__global__ void combine_kernel(const float* __restrict__ frac)
{
    int t = blockIdx.x, d = threadIdx.x;
    float acc = 0.f;
    #pragma unroll
    for (int view = 0; view < 3; view++)
        #pragma unroll
        for (int k = 0; k < KTOP; k++) {
            int slot = (view*TOKENS + t)*KTOP + k;
            float y = 0.f;
            #pragma unroll
            for (int s = 0; s < DSPLIT; s++)
                y += g_ypart[((size_t)s * NPAIR + slot)*DM + d];
            acc = fmaf(g_pw[slot], y, acc);
        }
    float fr = frac[t];
    int j; float r;
    if (d < 256) { j = d; r = fr; }
    else {
        j = d - 256;
        float l = log2f(fr);
        r = fminf(0.0025f * l * l, 1.0f);
    }
    r = fmaxf(r, 0.0002f);
    int idx = (int)rintf(r * 5000.0f) - 1;
    idx = max(0, min(4999, idx));
    double dv = pow(50.0, (double)(2*j) / 256.0);
    float pe = (float)((j & 1) ? cos((double)idx / dv) : sin((double)idx / dv));
    g_x[t*DM + d] = acc + pe;
}

// ---------------- attention (folds qkv split-K reduce + bias) ----------------
__global__ void attn_kernel(const float* __restrict__ part, const float* __restrict__ qb)
{
    int b = blockIdx.x, h = blockIdx.y;
    __shared__ float q[9][64], k[9][64], v[9][64], s[9][9];
    for (int i = threadIdx.x; i < 9*64; i += blockDim.x) {
        int l = i >> 6, d = i & 63;
        size_t row = (size_t)(b*9 + l)*1536 + h*64 + d;
        float qq = qb[h*64 + d], kk = qb[512 + h*64 + d], vv = qb[1024 + h*64 + d];
        #pragma unroll
        for (int sp = 0; sp < 4; sp++) {
            size_t o = (size_t)sp*TOKENS*1536 + row;
            qq += part[o]; kk += part[o + 512]; vv += part[o + 1024];
        }
        q[l][d] = qq; k[l][d] = kk; v[l][d] = vv;
    }
    __syncthreads();
    for (int i = threadIdx.x; i < 81; i += blockDim.x) {
        int qi = i / 9, kj = i % 9; float a = 0.f;
        #pragma unroll
        for (int d = 0; d < 64; d++) a = fmaf(q[qi][d], k[kj][d], a);
        s[qi][kj] = a * 0.125f;
    }
    __syncthreads();
    if (threadIdx.x < 9) {
        int i = threadIdx.x;
        float m = s[i][0];
        for (int jj = 1; jj < 9; jj++) m = fmaxf(m, s[i][jj]);
        float sum = 0.f;
        for (int jj = 0; jj < 9; jj++) { float ee = expf(s[i][jj] - m); s[i][jj] = ee; sum += ee; }
        float inv = 1.f / sum;
        for (int jj = 0; jj < 9; jj++) s[i][jj] *= inv;
    }
    __syncthreads();
    for (int i = threadIdx.x; i < 9*64; i += blockDim.x) {
        int l = i >> 6, d = i & 63; float a = 0.f;
        #pragma unroll
        for (int jj = 0; jj < 9; jj++) a = fmaf(s[l][jj], v[jj][d], a);
        g_attno[(size_t)(b*9 + l)*DM + h*64 + d] = a;
    }
}

// ---------------- split-K reduce + residual + LayerNorm ----------------
__device__ __forceinline__ float blockSum(float v, float* red)
{
    int lane = threadIdx.x & 31, w = threadIdx.x >> 5;
    #pragma unroll
    for (int o = 16; o; o >>= 1) v += __shfl_down_sync(0xffffffffu, v, o);
    if (lane == 0) red[w] = v;
    __syncthreads();
    if (threadIdx.x == 0) { float ss = 0.f; for (int i = 0; i < 8; i++) ss += red[i]; red[0] = ss; }
    __syncthreads();
    float r = red[0];
    __syncthreads();
    return r;
}

__global__ void reduce_addln_kernel(const float* __restrict__ part, int S,
                                    const float* __restrict__ bias,
                                    const float* __restrict__ gam, const float* __restrict__ bet,
                                    float* __restrict__ fout, const float* __restrict__ frac)
{
    int t = blockIdx.x, tid = threadIdx.x;
    __shared__ float red[8];
    float y0 = bias[tid], y1 = bias[tid + 256];
    for (int s = 0; s < S; s++) {
        y0 += part[((size_t)s*TOKENS + t)*DM + tid];
        y1 += part[((size_t)s*TOKENS + t)*DM + tid + 256];
    }
    float s0 = g_x[t*DM + tid] + y0;
    float s1 = g_x[t*DM + tid + 256] + y1;
    float mean = blockSum(s0 + s1, red) * (1.f/512.f);
    float d0 = s0 - mean, d1 = s1 - mean;
    float var = blockSum(d0*d0 + d1*d1, red) * (1.f/512.f);
    float inv = rsqrtf(var + 1e-5f);
    float r0 = d0*inv*gam[tid]       + bet[tid];
    float r1 = d1*inv*gam[tid + 256] + bet[tid + 256];
    if (fout) {
        float fr = frac[t];
        fout[t*DM + tid]       = r0 * fr;
        fout[t*DM + tid + 256] = r1 * fr;
    } else {
        g_x[t*DM + tid]       = r0;
        g_x[t*DM + tid + 256] = r1;
    }
}

// ---------------------------------- host ----------------------------------
extern "C" void kernel_launch(void* const* d_in, const int* in_sizes, int n_in,
                              void* d_out, int out_size)
{
    const int*   Z    = (const int*)d_in[0];
    const float* frac = (const float*)d_in[1];
    const float *emb0, *p0w, *p0b, *emb1, *p1w, *p1b, *emb2, *p2w, *p2b;
    if (in_sizes[3] == 200*512) {
        emb0 = (const float*)d_in[2]; p0w = (const float*)d_in[3]; p0b = (const float*)d_in[4];
        emb1 = (const float*)d_in[5]; p1w = (const float*)d_in[6]; p1b = (const float*)d_in[7];
        emb2 = (const float*)d_in[8]; p2w = (const float*)d_in[9]; p2b = (const float*)d_in[10];
    } else {
        emb0 = (const float*)d_in[2]; emb1 = (const float*)d_in[3]; emb2 = (const float*)d_in[4];
        p0w = (const float*)d_in[5]; p0b = (const float*)d_in[6];
        p1w = (const float*)d_in[7]; p1b = (const float*)d_in[8];
        p2w = (const float*)d_in[9]; p2b = (const float*)d_in[10];
    }
    const float* keys = (const float*)d_in[11];
    const float* rw   = (const float*)d_in[12];
    const float* rb   = (const float*)d_in[13];
    const float* ew1  = (const float*)d_in[14];
    const float* eb1  = (const float*)d_in[15];
    const float* ew2  = (const float*)d_in[16];
    const float* eb2  = (const float*)d_in[17];
    const float* qkvw = (const float*)d_in[18];
    const float* qkvb = (const float*)d_in[19];
    const float* aow  = (const float*)d_in[20];
    const float* aob  = (const float*)d_in[21];
    const float* l1g  = (const float*)d_in[22];
    const float* l1b  = (const float*)d_in[23];
    const float* l2g  = (const float*)d_in[24];
    const float* l2b  = (const float*)d_in[25];
    const float* f1w  = (const float*)d_in[26];
    const float* f1b  = (const float*)d_in[27];
    const float* f2w  = (const float*)d_in[28];
    const float* f2b  = (const float*)d_in[29];

    float *p_views, *p_h, *p_ypart, *p_part, *p_x, *p_attno, *p_hid;
    cudaGetSymbolAddress((void**)&p_views, g_views);
    cudaGetSymbolAddress((void**)&p_h,     g_h);
    cudaGetSymbolAddress((void**)&p_ypart, g_ypart);
    cudaGetSymbolAddress((void**)&p_part,  g_part);
    cudaGetSymbolAddress((void**)&p_x,     g_x);
    cudaGetSymbolAddress((void**)&p_attno, g_attno);
    cudaGetSymbolAddress((void**)&p_hid,   g_hid);

    zero_kernel<<<1, 32>>>();
    embed_route_kernel<<<dim3(TOKENS, 3), 256>>>(Z, emb0, p0w, p0b, emb1, p1w, p1b,
                                                 emb2, p2w, p2b, keys, rw, rb);

    // MoE up: gather + bias + gelu, full K=512
    gemm_kernel<1,1,1><<<dim3(HID/128, 8, NE), 256>>>(p_views, ew1, eb1, p_h, 0, HID, DM);
    // MoE down: split-K=4 over K=2048
    gemm_kernel<2,0,DSPLIT><<<dim3(DM/128, 8, NE*DSPLIT), 256>>>(p_h, ew2, eb2, p_ypart,
                                                                 0, DM, HID);
    combine_kernel<<<TOKENS, DM>>>(frac);

    for (int i = 0; i < 3; i++) {
        // qkv: split-K=4; reduce folded into attn
        gemm_kernel<0,0,4><<<dim3(12, 3, 4), 256>>>(p_x, qkvw + (size_t)i*DM*3*DM, nullptr,
                                                    p_part, TOKENS, 3*DM, DM);
        attn_kernel<<<dim3(32, 8), 128>>>(p_part, qkvb + (size_t)i*3*DM);
        // attn_out: split-K=8
        gemm_kernel<0,0,8><<<dim3(4, 3, 8), 256>>>(p_attno, aow + (size_t)i*DM*DM, nullptr,
                                                   p_part, TOKENS, DM, DM);
        reduce_addln_kernel<<<TOKENS, 256>>>(p_part, 8, aob + (size_t)i*DM,
                                             l1g + i*DM, l1b + i*DM, nullptr, nullptr);
        // ffn1: split-K=4, reduce+bias+relu -> g_hid
        gemm_kernel<0,0,4><<<dim3(16, 3, 4), 256>>>(p_x, f1w + (size_t)i*DM*HID, nullptr,
                                                    p_part, TOKENS, HID, DM);
        reduce_bias_kernel<2><<<(TOKENS*HID + 255)/256, 256>>>(p_part, f1b + (size_t)i*HID,
                                                               p_hid, TOKENS, HID, 4);
        // ffn2: split-K=16
        gemm_kernel<0,0,16><<<dim3(4, 3, 16), 256>>>(p_hid, f2w + (size_t)i*HID*DM, nullptr,
                                                     p_part, TOKENS, DM, HID);
        bool last = (i == 2);
        reduce_addln_kernel<<<TOKENS, 256>>>(p_part, 16, f2b + (size_t)i*DM,
                                             l2g + i*DM, l2b + i*DM,
                                             last ? (float*)d_out : nullptr,
                                             last ? frac : nullptr);
    }
}